// round 9
// baseline (speedup 1.0000x reference)
#include <cuda_runtime.h>
#include <cuda_bf16.h>
#include <cstdint>
#include <math.h>

#define BB 2
#define NN 2048
#define CC 384
#define HH 6
#define DD 64
#define TCC 1152   // 3*C
#define MM 4096    // B*N

typedef __nv_bfloat16 bf16;

// ---------------- device scratch ----------------
__device__ bf16 g_wqkv[TCC * CC];
__device__ bf16 g_wproj[CC * CC];
__device__ bf16 g_xq[(size_t)MM * CC];
__device__ bf16 g_q[BB * HH * NN * DD];
__device__ bf16 g_k[BB * HH * NN * DD];
__device__ bf16 g_v[BB * HH * NN * DD];
__device__ bf16 g_o[(size_t)MM * CC];

// ---------------- helpers ----------------
__device__ __forceinline__ float qlvl(float x, float inv_alpha) {
    float s = x * inv_alpha;
    s = fminf(fmaxf(s, -128.f), 127.f);
    return rintf(s);
}

__device__ __forceinline__ void mma16816(float* c, const uint32_t* a,
                                         uint32_t b0, uint32_t b1) {
    asm volatile(
        "mma.sync.aligned.m16n8k16.row.col.f32.bf16.bf16.f32 "
        "{%0,%1,%2,%3}, {%4,%5,%6,%7}, {%8,%9}, {%0,%1,%2,%3};\n"
        : "+f"(c[0]), "+f"(c[1]), "+f"(c[2]), "+f"(c[3])
        : "r"(a[0]), "r"(a[1]), "r"(a[2]), "r"(a[3]), "r"(b0), "r"(b1));
}

__device__ __forceinline__ uint32_t sptr(const void* p) {
    return (uint32_t)__cvta_generic_to_shared(p);
}

__device__ __forceinline__ void ldsm4(uint32_t* r, uint32_t addr) {
    asm volatile("ldmatrix.sync.aligned.m8n8.x4.shared.b16 {%0,%1,%2,%3},[%4];\n"
                 : "=r"(r[0]), "=r"(r[1]), "=r"(r[2]), "=r"(r[3]) : "r"(addr));
}

__device__ __forceinline__ void ldsm4t(uint32_t* r, uint32_t addr) {
    asm volatile("ldmatrix.sync.aligned.m8n8.x4.trans.shared.b16 {%0,%1,%2,%3},[%4];\n"
                 : "=r"(r[0]), "=r"(r[1]), "=r"(r[2]), "=r"(r[3]) : "r"(addr));
}

__device__ __forceinline__ void cpa16(uint32_t d, const void* s) {
    asm volatile("cp.async.cg.shared.global [%0], [%1], 16;\n" :: "r"(d), "l"(s));
}
__device__ __forceinline__ void cpcommit() {
    asm volatile("cp.async.commit_group;\n");
}
template <int N>
__device__ __forceinline__ void cpwait() {
    asm volatile("cp.async.wait_group %0;\n" :: "n"(N));
}

// ---------------- kernel 1: quantize weights + x to bf16 levels ----------------
__global__ __launch_bounds__(256) void k_quant(
        const float* __restrict__ x,
        const float* __restrict__ wqkv, const float* __restrict__ wproj,
        const float* __restrict__ a_qkv_w, const float* __restrict__ a_proj_w,
        const float* __restrict__ a_qkv_a) {
    float i1 = 1.f / a_qkv_w[0];
    float i2 = 1.f / a_proj_w[0];
    float i3 = 1.f / a_qkv_a[0];
    int i4 = (blockIdx.x * 256 + threadIdx.x) * 4;

    if (i4 < MM * CC) {
        float4 v = *(const float4*)&x[i4];
        __nv_bfloat162 p0, p1;
        p0.x = __float2bfloat16(qlvl(v.x, i3));
        p0.y = __float2bfloat16(qlvl(v.y, i3));
        p1.x = __float2bfloat16(qlvl(v.z, i3));
        p1.y = __float2bfloat16(qlvl(v.w, i3));
        *(__nv_bfloat162*)&g_xq[i4] = p0;
        *(__nv_bfloat162*)&g_xq[i4 + 2] = p1;
    }
    if (i4 < TCC * CC) {
        float4 v = *(const float4*)&wqkv[i4];
        __nv_bfloat162 p0, p1;
        p0.x = __float2bfloat16(qlvl(v.x, i1));
        p0.y = __float2bfloat16(qlvl(v.y, i1));
        p1.x = __float2bfloat16(qlvl(v.z, i1));
        p1.y = __float2bfloat16(qlvl(v.w, i1));
        *(__nv_bfloat162*)&g_wqkv[i4] = p0;
        *(__nv_bfloat162*)&g_wqkv[i4 + 2] = p1;
    }
    if (i4 < CC * CC) {
        float4 v = *(const float4*)&wproj[i4];
        __nv_bfloat162 p0, p1;
        p0.x = __float2bfloat16(qlvl(v.x, i2));
        p0.y = __float2bfloat16(qlvl(v.y, i2));
        p1.x = __float2bfloat16(qlvl(v.z, i2));
        p1.y = __float2bfloat16(qlvl(v.w, i2));
        *(__nv_bfloat162*)&g_wproj[i4] = p0;
        *(__nv_bfloat162*)&g_wproj[i4 + 2] = p1;
    }
}

// ---------------- kernel 2: QKV GEMM 4096x1152x384, CTA 64x128, cp.async pipelined ----------------
__global__ __launch_bounds__(256) void k_qkv(
        const float* __restrict__ a_qkv_a, const float* __restrict__ a_qkv_w,
        const float* __restrict__ a_q, const float* __restrict__ a_k,
        const float* __restrict__ a_v) {
    __shared__ bf16 sA[2][64][40];
    __shared__ bf16 sB[2][128][40];

    int tid = threadIdx.x, lane = tid & 31, wid = tid >> 5;
    int wm = wid & 3, wn = wid >> 2;
    int gr = lane >> 2, gc = (lane & 3) * 2;
    int lr_a = lane & 15, lc_a = (lane >> 4) << 3;
    int lr_b = ((lane >> 4) << 3) + (lane & 7), lc_b = ((lane >> 3) & 1) << 3;
    int m0 = blockIdx.x * 64, n0 = blockIdx.y * 128;

    int ra = tid >> 2, ca = (tid & 3) * 8;
    int rb = tid >> 2, cb = (tid & 3) * 8;

    float acc[8][4];
    #pragma unroll
    for (int i = 0; i < 8; i++)
        #pragma unroll
        for (int c = 0; c < 4; c++) acc[i][c] = 0.f;

    {
        cpa16(sptr(&sA[0][ra][ca]), &g_xq[(size_t)(m0 + ra) * CC + ca]);
        cpa16(sptr(&sB[0][rb][cb]), &g_wqkv[(size_t)(n0 + rb) * CC + cb]);
        cpa16(sptr(&sB[0][rb + 64][cb]), &g_wqkv[(size_t)(n0 + rb + 64) * CC + cb]);
        cpcommit();
    }

    for (int kt = 0; kt < 12; kt++) {
        int buf = kt & 1;
        if (kt < 11) {
            int nb2 = buf ^ 1, kc0 = (kt + 1) * 32;
            cpa16(sptr(&sA[nb2][ra][ca]), &g_xq[(size_t)(m0 + ra) * CC + kc0 + ca]);
            cpa16(sptr(&sB[nb2][rb][cb]), &g_wqkv[(size_t)(n0 + rb) * CC + kc0 + cb]);
            cpa16(sptr(&sB[nb2][rb + 64][cb]), &g_wqkv[(size_t)(n0 + rb + 64) * CC + kc0 + cb]);
            cpcommit();
            cpwait<1>();
        } else {
            cpwait<0>();
        }
        __syncthreads();
        #pragma unroll
        for (int kc = 0; kc < 2; kc++) {
            uint32_t af[4];
            ldsm4(af, sptr(&sA[buf][wm * 16 + lr_a][kc * 16 + lc_a]));
            #pragma unroll
            for (int np = 0; np < 4; np++) {
                uint32_t bfr[4];
                ldsm4(bfr, sptr(&sB[buf][wn * 64 + np * 16 + lr_b][kc * 16 + lc_b]));
                mma16816(acc[2 * np], af, bfr[0], bfr[1]);
                mma16816(acc[2 * np + 1], af, bfr[2], bfr[3]);
            }
        }
        __syncthreads();
    }

    int which = (n0 >= 768) ? 2 : (n0 >= 384 ? 1 : 0);
    const float* a3 = (which == 0) ? a_q : (which == 1 ? a_k : a_v);
    float inv3 = 1.f / a3[0];
    float sAB = a_qkv_a[0] * a_qkv_w[0];
    bf16* dst = (which == 0) ? g_q : (which == 1 ? g_k : g_v);
    int ncol0 = n0 - which * CC;
    #pragma unroll
    for (int nc = 0; nc < 8; nc++)
        #pragma unroll
        for (int h2 = 0; h2 < 2; h2++) {
            int row = m0 + wm * 16 + gr + h2 * 8;
            int col = ncol0 + wn * 64 + nc * 8 + gc;
            int b = row >> 11, n = row & 2047;
            int h = col >> 6, d = col & 63;
            __nv_bfloat162 pr;
            pr.x = __float2bfloat16(qlvl(acc[nc][2 * h2] * sAB, inv3));
            pr.y = __float2bfloat16(qlvl(acc[nc][2 * h2 + 1] * sAB, inv3));
            *(__nv_bfloat162*)&dst[(((size_t)(b * HH + h)) * NN + n) * DD + d] = pr;
        }
}

// ---------------- kernel 3: fused attention, 128 Q rows/CTA, 8 row-warps, fixed m ----------------
__global__ __launch_bounds__(256) void k_attn(
        const float* __restrict__ a_q, const float* __restrict__ a_k,
        const float* __restrict__ a_attn, const float* __restrict__ a_attn2,
        const float* __restrict__ a_v, const float* __restrict__ a_proj_a) {
    __shared__ bf16 sK[2][64][72];
    __shared__ bf16 sV[2][64][72];
    __shared__ float lut[256];

    int tid = threadIdx.x, lane = tid & 31, wid = tid >> 5;
    int gr = lane >> 2, gc = (lane & 3) * 2;
    int lr_a = lane & 15, lc_a = (lane >> 4) << 3;
    int lr_b = ((lane >> 4) << 3) + (lane & 7), lc_b = ((lane >> 3) & 1) << 3;
    int bh = blockIdx.y;
    int rt0 = blockIdx.x * 128;
    int wr = wid * 16;          // 0..112: each warp owns 16 rows, full 64 cols

    float aat = a_attn[0];
    float fsc = a_q[0] * a_k[0] * 0.125f / aat;   // scale = D^-0.5 = 1/8

    lut[tid] = expf(-(float)tid * aat);

    const bf16* kbase = g_k + (size_t)bh * NN * DD;
    const bf16* vbase = g_v + (size_t)bh * NN * DD;

    // stage Q (128x64) across sK[0] (rows 0-63) and sK[1] (rows 64-127)
    const bf16* qptr = g_q + ((size_t)bh * NN + rt0) * DD;
    #pragma unroll
    for (int t = 0; t < 4; t++) {
        int idx = tid + t * 256;
        int r = idx >> 3, c8 = (idx & 7) * 8;
        bf16* dst = (r < 64) ? &sK[0][r][c8] : &sK[1][r - 64][c8];
        *(uint4*)dst = *(const uint4*)&qptr[(size_t)r * DD + c8];
    }
    __syncthreads();
    uint32_t qf[4][4];
    {
        bf16(*qsrc)[72] = (wid < 4) ? sK[0] : sK[1];
        int qr = wr & 63;
        #pragma unroll
        for (int kc = 0; kc < 4; kc++)
            ldsm4(qf[kc], sptr(&qsrc[qr + lr_a][kc * 16 + lc_a]));
    }
    __syncthreads();

    float tl[2] = {0.f, 0.f};

    // prefetch K tile 0
    #pragma unroll
    for (int t = 0; t < 2; t++) {
        int idx = tid + t * 256;
        int r = idx >> 3, c8 = (idx & 7) * 8;
        cpa16(sptr(&sK[0][r][c8]), &kbase[(size_t)r * DD + c8]);
    }
    cpcommit();

    // ---------- pass 1: row sums of exp((l-127)*a) ----------
    for (int ct = 0; ct < 32; ct++) {
        int buf = ct & 1;
        if (ct < 31) {
            const bf16* kp = kbase + (size_t)(ct + 1) * 64 * DD;
            #pragma unroll
            for (int t = 0; t < 2; t++) {
                int idx = tid + t * 256;
                int r = idx >> 3, c8 = (idx & 7) * 8;
                cpa16(sptr(&sK[buf ^ 1][r][c8]), &kp[(size_t)r * DD + c8]);
            }
            cpcommit();
            cpwait<1>();
        } else {
            cpwait<0>();
        }
        __syncthreads();

        float sacc[8][4];
        #pragma unroll
        for (int i = 0; i < 8; i++)
            #pragma unroll
            for (int c = 0; c < 4; c++) sacc[i][c] = 0.f;
        #pragma unroll
        for (int ks = 0; ks < 4; ks++)
            #pragma unroll
            for (int np = 0; np < 4; np++) {
                uint32_t bfr[4];
                ldsm4(bfr, sptr(&sK[buf][np * 16 + lr_b][ks * 16 + lc_b]));
                mma16816(sacc[2 * np], qf[ks], bfr[0], bfr[1]);
                mma16816(sacc[2 * np + 1], qf[ks], bfr[2], bfr[3]);
            }

        #pragma unroll
        for (int nc = 0; nc < 8; nc++)
            #pragma unroll
            for (int h2 = 0; h2 < 2; h2++) {
                int l0 = __float2int_rn(fminf(fmaxf(sacc[nc][2 * h2] * fsc, -128.f), 127.f));
                int l1 = __float2int_rn(fminf(fmaxf(sacc[nc][2 * h2 + 1] * fsc, -128.f), 127.f));
                tl[h2] += lut[127 - l0] + lut[127 - l1];
            }
        __syncthreads();
    }

    // quad reduce (lanes of a quad share the row) -> per-row sums, lane-local
    float inva2 = 1.f / a_attn2[0];
    float liq[2];
    #pragma unroll
    for (int h2 = 0; h2 < 2; h2++) {
        tl[h2] += __shfl_xor_sync(0xffffffff, tl[h2], 1);
        tl[h2] += __shfl_xor_sync(0xffffffff, tl[h2], 2);
        liq[h2] = inva2 / tl[h2];
    }

    // prefetch K+V tile 0 for pass 2
    #pragma unroll
    for (int t = 0; t < 2; t++) {
        int idx = tid + t * 256;
        int r = idx >> 3, c8 = (idx & 7) * 8;
        cpa16(sptr(&sK[0][r][c8]), &kbase[(size_t)r * DD + c8]);
        cpa16(sptr(&sV[0][r][c8]), &vbase[(size_t)r * DD + c8]);
    }
    cpcommit();

    // ---------- pass 2: recompute S, P in registers, P*V ----------
    float oacc[8][4];
    #pragma unroll
    for (int i = 0; i < 8; i++)
        #pragma unroll
        for (int c = 0; c < 4; c++) oacc[i][c] = 0.f;

    for (int ct = 0; ct < 32; ct++) {
        int buf = ct & 1;
        if (ct < 31) {
            const bf16* kp = kbase + (size_t)(ct + 1) * 64 * DD;
            const bf16* vp = vbase + (size_t)(ct + 1) * 64 * DD;
            #pragma unroll
            for (int t = 0; t < 2; t++) {
                int idx = tid + t * 256;
                int r = idx >> 3, c8 = (idx & 7) * 8;
                cpa16(sptr(&sK[buf ^ 1][r][c8]), &kp[(size_t)r * DD + c8]);
                cpa16(sptr(&sV[buf ^ 1][r][c8]), &vp[(size_t)r * DD + c8]);
            }
            cpcommit();
            cpwait<1>();
        } else {
            cpwait<0>();
        }
        __syncthreads();

        float sacc[8][4];
        #pragma unroll
        for (int i = 0; i < 8; i++)
            #pragma unroll
            for (int c = 0; c < 4; c++) sacc[i][c] = 0.f;
        #pragma unroll
        for (int ks = 0; ks < 4; ks++)
            #pragma unroll
            for (int np = 0; np < 4; np++) {
                uint32_t bfr[4];
                ldsm4(bfr, sptr(&sK[buf][np * 16 + lr_b][ks * 16 + lc_b]));
                mma16816(sacc[2 * np], qf[ks], bfr[0], bfr[1]);
                mma16816(sacc[2 * np + 1], qf[ks], bfr[2], bfr[3]);
            }

        // S fragments (f32) -> P level fragments (bf16 A-layout), in registers
        uint32_t pf[4][4];
        #pragma unroll
        for (int kc = 0; kc < 4; kc++) {
            int nc = 2 * kc, ncb = 2 * kc + 1;
            #pragma unroll
            for (int slot = 0; slot < 4; slot++) {
                int src = (slot & 2) ? ncb : nc;
                int h2 = slot & 1;
                float s0 = (h2 ? sacc[src][2] : sacc[src][0]);
                float s1 = (h2 ? sacc[src][3] : sacc[src][1]);
                int l0 = __float2int_rn(fminf(fmaxf(s0 * fsc, -128.f), 127.f));
                int l1 = __float2int_rn(fminf(fmaxf(s1 * fsc, -128.f), 127.f));
                float p0 = rintf(fminf(lut[127 - l0] * liq[h2], 127.f));
                float p1 = rintf(fminf(lut[127 - l1] * liq[h2], 127.f));
                __nv_bfloat162 pr;
                pr.x = __float2bfloat16(p0);
                pr.y = __float2bfloat16(p1);
                pf[kc][slot] = *(uint32_t*)&pr;
            }
        }

        // P (16x64) x V (64x64): B fragments via ldmatrix.trans
        #pragma unroll
        for (int ks = 0; ks < 4; ks++)
            #pragma unroll
            for (int np = 0; np < 4; np++) {
                uint32_t bfr[4];
                ldsm4t(bfr, sptr(&sV[buf][ks * 16 + lr_a][np * 16 + lc_a]));
                mma16816(oacc[2 * np], pf[ks], bfr[0], bfr[1]);
                mma16816(oacc[2 * np + 1], pf[ks], bfr[2], bfr[3]);
            }
        __syncthreads();
    }

    // epilogue: scale by a_attn2*a_v, quantize with a_proj_a, store [B,N,C] levels
    int b = bh / HH, h = bh % HH;
    float so = a_attn2[0] * a_v[0];
    float invpa = 1.f / a_proj_a[0];
    #pragma unroll
    for (int nc = 0; nc < 8; nc++)
        #pragma unroll
        for (int h2 = 0; h2 < 2; h2++) {
            int n = rt0 + wr + gr + h2 * 8;
            int d = nc * 8 + gc;
            __nv_bfloat162 pr;
            pr.x = __float2bfloat16(qlvl(oacc[nc][2 * h2] * so, invpa));
            pr.y = __float2bfloat16(qlvl(oacc[nc][2 * h2 + 1] * so, invpa));
            *(__nv_bfloat162*)&g_o[((size_t)(b * NN + n)) * CC + h * 64 + d] = pr;
        }
}

// ---------------- kernel 4: projection GEMM 4096x384x384 + bias, CTA 64x64 ----------------
__global__ __launch_bounds__(256) void k_proj(
        float* __restrict__ out, const float* __restrict__ bproj,
        const float* __restrict__ a_proj_a, const float* __restrict__ a_proj_w) {
    __shared__ bf16 sA[2][64][40];
    __shared__ bf16 sB[2][64][40];

    int tid = threadIdx.x, lane = tid & 31, wid = tid >> 5;
    int wm = wid & 3, wn = wid >> 2;
    int gr = lane >> 2, gc = (lane & 3) * 2;
    int lr_a = lane & 15, lc_a = (lane >> 4) << 3;
    int lr_b = ((lane >> 4) << 3) + (lane & 7), lc_b = ((lane >> 3) & 1) << 3;
    int m0 = blockIdx.x * 64, n0 = blockIdx.y * 64;

    int ra = tid >> 2, ca = (tid & 3) * 8;

    float acc[4][4];
    #pragma unroll
    for (int i = 0; i < 4; i++)
        #pragma unroll
        for (int c = 0; c < 4; c++) acc[i][c] = 0.f;

    {
        cpa16(sptr(&sA[0][ra][ca]), &g_o[(size_t)(m0 + ra) * CC + ca]);
        cpa16(sptr(&sB[0][ra][ca]), &g_wproj[(size_t)(n0 + ra) * CC + ca]);
        cpcommit();
    }

    for (int kt = 0; kt < 12; kt++) {
        int buf = kt & 1;
        if (kt < 11) {
            int nb2 = buf ^ 1, kc0 = (kt + 1) * 32;
            cpa16(sptr(&sA[nb2][ra][ca]), &g_o[(size_t)(m0 + ra) * CC + kc0 + ca]);
            cpa16(sptr(&sB[nb2][ra][ca]), &g_wproj[(size_t)(n0 + ra) * CC + kc0 + ca]);
            cpcommit();
            cpwait<1>();
        } else {
            cpwait<0>();
        }
        __syncthreads();
        #pragma unroll
        for (int kc = 0; kc < 2; kc++) {
            uint32_t af[4];
            ldsm4(af, sptr(&sA[buf][wm * 16 + lr_a][kc * 16 + lc_a]));
            #pragma unroll
            for (int np = 0; np < 2; np++) {
                uint32_t bfr[4];
                ldsm4(bfr, sptr(&sB[buf][wn * 32 + np * 16 + lr_b][kc * 16 + lc_b]));
                mma16816(acc[2 * np], af, bfr[0], bfr[1]);
                mma16816(acc[2 * np + 1], af, bfr[2], bfr[3]);
            }
        }
        __syncthreads();
    }

    float sc = a_proj_a[0] * a_proj_w[0];
    #pragma unroll
    for (int jj = 0; jj < 4; jj++)
        #pragma unroll
        for (int h2 = 0; h2 < 2; h2++) {
            int row = m0 + wm * 16 + gr + h2 * 8;
            int col = n0 + wn * 32 + jj * 8 + gc;
            float2 r2;
            r2.x = acc[jj][2 * h2] * sc + bproj[col];
            r2.y = acc[jj][2 * h2 + 1] * sc + bproj[col + 1];
            *(float2*)&out[(size_t)row * CC + col] = r2;
        }
}

// ---------------- launch ----------------
extern "C" void kernel_launch(void* const* d_in, const int* in_sizes, int n_in,
                              void* d_out, int out_size) {
    const float* x        = (const float*)d_in[0];
    const float* wqkv     = (const float*)d_in[1];
    const float* wproj    = (const float*)d_in[2];
    const float* bproj    = (const float*)d_in[3];
    const float* a_qkv_w  = (const float*)d_in[4];
    const float* a_qkv_a  = (const float*)d_in[5];
    const float* a_proj_w = (const float*)d_in[6];
    const float* a_proj_a = (const float*)d_in[7];
    const float* a_q      = (const float*)d_in[8];
    const float* a_k      = (const float*)d_in[9];
    const float* a_v      = (const float*)d_in[10];
    const float* a_attn   = (const float*)d_in[11];
    const float* a_attn2  = (const float*)d_in[12];
    float* out = (float*)d_out;

    k_quant<<<(MM * CC / 4 + 255) / 256, 256>>>(x, wqkv, wproj, a_qkv_w, a_proj_w, a_qkv_a);
    k_qkv<<<dim3(64, 9), 256>>>(a_qkv_a, a_qkv_w, a_q, a_k, a_v);
    k_attn<<<dim3(16, 12), 256>>>(a_q, a_k, a_attn, a_attn2, a_v, a_proj_a);
    k_proj<<<dim3(64, 6), 256>>>(out, bproj, a_proj_a, a_proj_w);
}

// round 10
// speedup vs baseline: 1.1605x; 1.1605x over previous
#include <cuda_runtime.h>
#include <cuda_bf16.h>
#include <cstdint>
#include <math.h>

#define BB 2
#define NN 2048
#define CC 384
#define HH 6
#define DD 64
#define TCC 1152   // 3*C
#define MM 4096    // B*N

typedef __nv_bfloat16 bf16;

// ---------------- device scratch ----------------
__device__ bf16 g_wqkv[TCC * CC];
__device__ bf16 g_wproj[CC * CC];
__device__ bf16 g_xq[(size_t)MM * CC];
__device__ bf16 g_q[BB * HH * NN * DD];
__device__ bf16 g_k[BB * HH * NN * DD];
__device__ bf16 g_v[BB * HH * NN * DD];
__device__ bf16 g_o[(size_t)MM * CC];

// ---------------- helpers ----------------
__device__ __forceinline__ float qlvl(float x, float inv_alpha) {
    float s = x * inv_alpha;
    s = fminf(fmaxf(s, -128.f), 127.f);
    return rintf(s);
}

__device__ __forceinline__ void mma16816(float* c, const uint32_t* a,
                                         uint32_t b0, uint32_t b1) {
    asm volatile(
        "mma.sync.aligned.m16n8k16.row.col.f32.bf16.bf16.f32 "
        "{%0,%1,%2,%3}, {%4,%5,%6,%7}, {%8,%9}, {%0,%1,%2,%3};\n"
        : "+f"(c[0]), "+f"(c[1]), "+f"(c[2]), "+f"(c[3])
        : "r"(a[0]), "r"(a[1]), "r"(a[2]), "r"(a[3]), "r"(b0), "r"(b1));
}

__device__ __forceinline__ uint32_t sptr(const void* p) {
    return (uint32_t)__cvta_generic_to_shared(p);
}

__device__ __forceinline__ void ldsm4(uint32_t* r, uint32_t addr) {
    asm volatile("ldmatrix.sync.aligned.m8n8.x4.shared.b16 {%0,%1,%2,%3},[%4];\n"
                 : "=r"(r[0]), "=r"(r[1]), "=r"(r[2]), "=r"(r[3]) : "r"(addr));
}

__device__ __forceinline__ void ldsm4t(uint32_t* r, uint32_t addr) {
    asm volatile("ldmatrix.sync.aligned.m8n8.x4.trans.shared.b16 {%0,%1,%2,%3},[%4];\n"
                 : "=r"(r[0]), "=r"(r[1]), "=r"(r[2]), "=r"(r[3]) : "r"(addr));
}

__device__ __forceinline__ void cpa16(uint32_t d, const void* s) {
    asm volatile("cp.async.cg.shared.global [%0], [%1], 16;\n" :: "r"(d), "l"(s));
}
__device__ __forceinline__ void cpcommit() {
    asm volatile("cp.async.commit_group;\n");
}
template <int N>
__device__ __forceinline__ void cpwait() {
    asm volatile("cp.async.wait_group %0;\n" :: "n"(N));
}

// ---------------- kernel 1: quantize weights + x to bf16 levels ----------------
__global__ __launch_bounds__(256) void k_quant(
        const float* __restrict__ x,
        const float* __restrict__ wqkv, const float* __restrict__ wproj,
        const float* __restrict__ a_qkv_w, const float* __restrict__ a_proj_w,
        const float* __restrict__ a_qkv_a) {
    float i1 = 1.f / a_qkv_w[0];
    float i2 = 1.f / a_proj_w[0];
    float i3 = 1.f / a_qkv_a[0];
    int i4 = (blockIdx.x * 256 + threadIdx.x) * 4;

    if (i4 < MM * CC) {
        float4 v = *(const float4*)&x[i4];
        __nv_bfloat162 p0, p1;
        p0.x = __float2bfloat16(qlvl(v.x, i3));
        p0.y = __float2bfloat16(qlvl(v.y, i3));
        p1.x = __float2bfloat16(qlvl(v.z, i3));
        p1.y = __float2bfloat16(qlvl(v.w, i3));
        *(__nv_bfloat162*)&g_xq[i4] = p0;
        *(__nv_bfloat162*)&g_xq[i4 + 2] = p1;
    }
    if (i4 < TCC * CC) {
        float4 v = *(const float4*)&wqkv[i4];
        __nv_bfloat162 p0, p1;
        p0.x = __float2bfloat16(qlvl(v.x, i1));
        p0.y = __float2bfloat16(qlvl(v.y, i1));
        p1.x = __float2bfloat16(qlvl(v.z, i1));
        p1.y = __float2bfloat16(qlvl(v.w, i1));
        *(__nv_bfloat162*)&g_wqkv[i4] = p0;
        *(__nv_bfloat162*)&g_wqkv[i4 + 2] = p1;
    }
    if (i4 < CC * CC) {
        float4 v = *(const float4*)&wproj[i4];
        __nv_bfloat162 p0, p1;
        p0.x = __float2bfloat16(qlvl(v.x, i2));
        p0.y = __float2bfloat16(qlvl(v.y, i2));
        p1.x = __float2bfloat16(qlvl(v.z, i2));
        p1.y = __float2bfloat16(qlvl(v.w, i2));
        *(__nv_bfloat162*)&g_wproj[i4] = p0;
        *(__nv_bfloat162*)&g_wproj[i4 + 2] = p1;
    }
}

// ---------------- kernel 2: QKV GEMM 4096x1152x384, CTA 64x128, cp.async pipelined ----------------
__global__ __launch_bounds__(256) void k_qkv(
        const float* __restrict__ a_qkv_a, const float* __restrict__ a_qkv_w,
        const float* __restrict__ a_q, const float* __restrict__ a_k,
        const float* __restrict__ a_v) {
    __shared__ bf16 sA[2][64][40];
    __shared__ bf16 sB[2][128][40];

    int tid = threadIdx.x, lane = tid & 31, wid = tid >> 5;
    int wm = wid & 3, wn = wid >> 2;
    int gr = lane >> 2, gc = (lane & 3) * 2;
    int lr_a = lane & 15, lc_a = (lane >> 4) << 3;
    int lr_b = ((lane >> 4) << 3) + (lane & 7), lc_b = ((lane >> 3) & 1) << 3;
    int m0 = blockIdx.x * 64, n0 = blockIdx.y * 128;

    int ra = tid >> 2, ca = (tid & 3) * 8;
    int rb = tid >> 2, cb = (tid & 3) * 8;

    float acc[8][4];
    #pragma unroll
    for (int i = 0; i < 8; i++)
        #pragma unroll
        for (int c = 0; c < 4; c++) acc[i][c] = 0.f;

    {
        cpa16(sptr(&sA[0][ra][ca]), &g_xq[(size_t)(m0 + ra) * CC + ca]);
        cpa16(sptr(&sB[0][rb][cb]), &g_wqkv[(size_t)(n0 + rb) * CC + cb]);
        cpa16(sptr(&sB[0][rb + 64][cb]), &g_wqkv[(size_t)(n0 + rb + 64) * CC + cb]);
        cpcommit();
    }

    for (int kt = 0; kt < 12; kt++) {
        int buf = kt & 1;
        if (kt < 11) {
            int nb2 = buf ^ 1, kc0 = (kt + 1) * 32;
            cpa16(sptr(&sA[nb2][ra][ca]), &g_xq[(size_t)(m0 + ra) * CC + kc0 + ca]);
            cpa16(sptr(&sB[nb2][rb][cb]), &g_wqkv[(size_t)(n0 + rb) * CC + kc0 + cb]);
            cpa16(sptr(&sB[nb2][rb + 64][cb]), &g_wqkv[(size_t)(n0 + rb + 64) * CC + kc0 + cb]);
            cpcommit();
            cpwait<1>();
        } else {
            cpwait<0>();
        }
        __syncthreads();
        #pragma unroll
        for (int kc = 0; kc < 2; kc++) {
            uint32_t af[4];
            ldsm4(af, sptr(&sA[buf][wm * 16 + lr_a][kc * 16 + lc_a]));
            #pragma unroll
            for (int np = 0; np < 4; np++) {
                uint32_t bfr[4];
                ldsm4(bfr, sptr(&sB[buf][wn * 64 + np * 16 + lr_b][kc * 16 + lc_b]));
                mma16816(acc[2 * np], af, bfr[0], bfr[1]);
                mma16816(acc[2 * np + 1], af, bfr[2], bfr[3]);
            }
        }
        __syncthreads();
    }

    int which = (n0 >= 768) ? 2 : (n0 >= 384 ? 1 : 0);
    const float* a3 = (which == 0) ? a_q : (which == 1 ? a_k : a_v);
    float inv3 = 1.f / a3[0];
    float sAB = a_qkv_a[0] * a_qkv_w[0];
    bf16* dst = (which == 0) ? g_q : (which == 1 ? g_k : g_v);
    int ncol0 = n0 - which * CC;
    #pragma unroll
    for (int nc = 0; nc < 8; nc++)
        #pragma unroll
        for (int h2 = 0; h2 < 2; h2++) {
            int row = m0 + wm * 16 + gr + h2 * 8;
            int col = ncol0 + wn * 64 + nc * 8 + gc;
            int b = row >> 11, n = row & 2047;
            int h = col >> 6, d = col & 63;
            __nv_bfloat162 pr;
            pr.x = __float2bfloat16(qlvl(acc[nc][2 * h2] * sAB, inv3));
            pr.y = __float2bfloat16(qlvl(acc[nc][2 * h2 + 1] * sAB, inv3));
            *(__nv_bfloat162*)&dst[(((size_t)(b * HH + h)) * NN + n) * DD + d] = pr;
        }
}

// ---------------- kernel 3: fused attention, 64 Q rows/CTA, 4 warps, fixed m ----------------
__global__ __launch_bounds__(128) void k_attn(
        const float* __restrict__ a_q, const float* __restrict__ a_k,
        const float* __restrict__ a_attn, const float* __restrict__ a_attn2,
        const float* __restrict__ a_v, const float* __restrict__ a_proj_a) {
    __shared__ bf16 sK[2][64][72];
    __shared__ bf16 sV[2][64][72];
    __shared__ float lut[256];

    int tid = threadIdx.x, lane = tid & 31, wid = tid >> 5;
    int gr = lane >> 2, gc = (lane & 3) * 2;
    int lr_a = lane & 15, lc_a = (lane >> 4) << 3;
    int lr_b = ((lane >> 4) << 3) + (lane & 7), lc_b = ((lane >> 3) & 1) << 3;
    int bh = blockIdx.y;
    int rt0 = blockIdx.x * 64;
    int wr = wid * 16;

    float aat = a_attn[0];
    float fsc = a_q[0] * a_k[0] * 0.125f / aat;   // scale = D^-0.5 = 1/8

    #pragma unroll
    for (int i = tid; i < 256; i += 128) lut[i] = expf(-(float)i * aat);

    const bf16* kbase = g_k + (size_t)bh * NN * DD;
    const bf16* vbase = g_v + (size_t)bh * NN * DD;

    // stage Q into sK[0], build resident A fragments
    const bf16* qptr = g_q + ((size_t)bh * NN + rt0) * DD;
    #pragma unroll
    for (int t = 0; t < 4; t++) {
        int idx = tid + t * 128;
        int r = idx >> 3, c8 = (idx & 7) * 8;
        *(uint4*)&sK[0][r][c8] = *(const uint4*)&qptr[(size_t)r * DD + c8];
    }
    __syncthreads();
    uint32_t qf[4][4];
    #pragma unroll
    for (int kc = 0; kc < 4; kc++)
        ldsm4(qf[kc], sptr(&sK[0][wr + lr_a][kc * 16 + lc_a]));
    __syncthreads();

    float tl[2] = {0.f, 0.f};

    // prefetch K tile 0
    #pragma unroll
    for (int t = 0; t < 4; t++) {
        int idx = tid + t * 128;
        int r = idx >> 3, c8 = (idx & 7) * 8;
        cpa16(sptr(&sK[0][r][c8]), &kbase[(size_t)r * DD + c8]);
    }
    cpcommit();

    // ---------- pass 1: row sums of exp((l-127)*a) ----------
    for (int ct = 0; ct < 32; ct++) {
        int buf = ct & 1;
        if (ct < 31) {
            const bf16* kp = kbase + (size_t)(ct + 1) * 64 * DD;
            #pragma unroll
            for (int t = 0; t < 4; t++) {
                int idx = tid + t * 128;
                int r = idx >> 3, c8 = (idx & 7) * 8;
                cpa16(sptr(&sK[buf ^ 1][r][c8]), &kp[(size_t)r * DD + c8]);
            }
            cpcommit();
            cpwait<1>();
        } else {
            cpwait<0>();
        }
        __syncthreads();

        float sacc[8][4];
        #pragma unroll
        for (int i = 0; i < 8; i++)
            #pragma unroll
            for (int c = 0; c < 4; c++) sacc[i][c] = 0.f;
        #pragma unroll
        for (int ks = 0; ks < 4; ks++)
            #pragma unroll
            for (int np = 0; np < 4; np++) {
                uint32_t bfr[4];
                ldsm4(bfr, sptr(&sK[buf][np * 16 + lr_b][ks * 16 + lc_b]));
                mma16816(sacc[2 * np], qf[ks], bfr[0], bfr[1]);
                mma16816(sacc[2 * np + 1], qf[ks], bfr[2], bfr[3]);
            }

        #pragma unroll
        for (int nc = 0; nc < 8; nc++)
            #pragma unroll
            for (int h2 = 0; h2 < 2; h2++) {
                int l0 = __float2int_rn(fminf(fmaxf(sacc[nc][2 * h2] * fsc, -128.f), 127.f));
                int l1 = __float2int_rn(fminf(fmaxf(sacc[nc][2 * h2 + 1] * fsc, -128.f), 127.f));
                tl[h2] += lut[127 - l0] + lut[127 - l1];
            }
        __syncthreads();
    }

    // quad sum-reduce (lanes of a quad share the row) -> lane-local inverse sums
    float inva2 = 1.f / a_attn2[0];
    float liq[2];
    #pragma unroll
    for (int h2 = 0; h2 < 2; h2++) {
        tl[h2] += __shfl_xor_sync(0xffffffff, tl[h2], 1);
        tl[h2] += __shfl_xor_sync(0xffffffff, tl[h2], 2);
        liq[h2] = inva2 / tl[h2];
    }

    // prefetch K+V tile 0 for pass 2
    #pragma unroll
    for (int t = 0; t < 4; t++) {
        int idx = tid + t * 128;
        int r = idx >> 3, c8 = (idx & 7) * 8;
        cpa16(sptr(&sK[0][r][c8]), &kbase[(size_t)r * DD + c8]);
        cpa16(sptr(&sV[0][r][c8]), &vbase[(size_t)r * DD + c8]);
    }
    cpcommit();

    // ---------- pass 2: recompute S, P in registers, P*V ----------
    float oacc[8][4];
    #pragma unroll
    for (int i = 0; i < 8; i++)
        #pragma unroll
        for (int c = 0; c < 4; c++) oacc[i][c] = 0.f;

    for (int ct = 0; ct < 32; ct++) {
        int buf = ct & 1;
        if (ct < 31) {
            const bf16* kp = kbase + (size_t)(ct + 1) * 64 * DD;
            const bf16* vp = vbase + (size_t)(ct + 1) * 64 * DD;
            #pragma unroll
            for (int t = 0; t < 4; t++) {
                int idx = tid + t * 128;
                int r = idx >> 3, c8 = (idx & 7) * 8;
                cpa16(sptr(&sK[buf ^ 1][r][c8]), &kp[(size_t)r * DD + c8]);
                cpa16(sptr(&sV[buf ^ 1][r][c8]), &vp[(size_t)r * DD + c8]);
            }
            cpcommit();
            cpwait<1>();
        } else {
            cpwait<0>();
        }
        __syncthreads();

        float sacc[8][4];
        #pragma unroll
        for (int i = 0; i < 8; i++)
            #pragma unroll
            for (int c = 0; c < 4; c++) sacc[i][c] = 0.f;
        #pragma unroll
        for (int ks = 0; ks < 4; ks++)
            #pragma unroll
            for (int np = 0; np < 4; np++) {
                uint32_t bfr[4];
                ldsm4(bfr, sptr(&sK[buf][np * 16 + lr_b][ks * 16 + lc_b]));
                mma16816(sacc[2 * np], qf[ks], bfr[0], bfr[1]);
                mma16816(sacc[2 * np + 1], qf[ks], bfr[2], bfr[3]);
            }

        // S fragments (f32) -> P level fragments (bf16 A-layout), in registers
        uint32_t pf[4][4];
        #pragma unroll
        for (int kc = 0; kc < 4; kc++) {
            int nc = 2 * kc, ncb = 2 * kc + 1;
            #pragma unroll
            for (int slot = 0; slot < 4; slot++) {
                int src = (slot & 2) ? ncb : nc;
                int h2 = slot & 1;
                float s0 = (h2 ? sacc[src][2] : sacc[src][0]);
                float s1 = (h2 ? sacc[src][3] : sacc[src][1]);
                int l0 = __float2int_rn(fminf(fmaxf(s0 * fsc, -128.f), 127.f));
                int l1 = __float2int_rn(fminf(fmaxf(s1 * fsc, -128.f), 127.f));
                float p0 = rintf(fminf(lut[127 - l0] * liq[h2], 127.f));
                float p1 = rintf(fminf(lut[127 - l1] * liq[h2], 127.f));
                __nv_bfloat162 pr;
                pr.x = __float2bfloat16(p0);
                pr.y = __float2bfloat16(p1);
                pf[kc][slot] = *(uint32_t*)&pr;
            }
        }

        // P (16x64) x V (64x64): B fragments via ldmatrix.trans
        #pragma unroll
        for (int ks = 0; ks < 4; ks++)
            #pragma unroll
            for (int np = 0; np < 4; np++) {
                uint32_t bfr[4];
                ldsm4t(bfr, sptr(&sV[buf][ks * 16 + lr_a][np * 16 + lc_a]));
                mma16816(oacc[2 * np], pf[ks], bfr[0], bfr[1]);
                mma16816(oacc[2 * np + 1], pf[ks], bfr[2], bfr[3]);
            }
        __syncthreads();
    }

    // epilogue: scale by a_attn2*a_v, quantize with a_proj_a, store [B,N,C] levels
    int b = bh / HH, h = bh % HH;
    float so = a_attn2[0] * a_v[0];
    float invpa = 1.f / a_proj_a[0];
    #pragma unroll
    for (int nc = 0; nc < 8; nc++)
        #pragma unroll
        for (int h2 = 0; h2 < 2; h2++) {
            int n = rt0 + wr + gr + h2 * 8;
            int d = nc * 8 + gc;
            __nv_bfloat162 pr;
            pr.x = __float2bfloat16(qlvl(oacc[nc][2 * h2] * so, invpa));
            pr.y = __float2bfloat16(qlvl(oacc[nc][2 * h2 + 1] * so, invpa));
            *(__nv_bfloat162*)&g_o[((size_t)(b * NN + n)) * CC + h * 64 + d] = pr;
        }
}

// ---------------- kernel 4: projection GEMM 4096x384x384 + bias, CTA 64x64 ----------------
__global__ __launch_bounds__(256) void k_proj(
        float* __restrict__ out, const float* __restrict__ bproj,
        const float* __restrict__ a_proj_a, const float* __restrict__ a_proj_w) {
    __shared__ bf16 sA[2][64][40];
    __shared__ bf16 sB[2][64][40];

    int tid = threadIdx.x, lane = tid & 31, wid = tid >> 5;
    int wm = wid & 3, wn = wid >> 2;
    int gr = lane >> 2, gc = (lane & 3) * 2;
    int lr_a = lane & 15, lc_a = (lane >> 4) << 3;
    int lr_b = ((lane >> 4) << 3) + (lane & 7), lc_b = ((lane >> 3) & 1) << 3;
    int m0 = blockIdx.x * 64, n0 = blockIdx.y * 64;

    int ra = tid >> 2, ca = (tid & 3) * 8;

    float acc[4][4];
    #pragma unroll
    for (int i = 0; i < 4; i++)
        #pragma unroll
        for (int c = 0; c < 4; c++) acc[i][c] = 0.f;

    {
        cpa16(sptr(&sA[0][ra][ca]), &g_o[(size_t)(m0 + ra) * CC + ca]);
        cpa16(sptr(&sB[0][ra][ca]), &g_wproj[(size_t)(n0 + ra) * CC + ca]);
        cpcommit();
    }

    for (int kt = 0; kt < 12; kt++) {
        int buf = kt & 1;
        if (kt < 11) {
            int nb2 = buf ^ 1, kc0 = (kt + 1) * 32;
            cpa16(sptr(&sA[nb2][ra][ca]), &g_o[(size_t)(m0 + ra) * CC + kc0 + ca]);
            cpa16(sptr(&sB[nb2][ra][ca]), &g_wproj[(size_t)(n0 + ra) * CC + kc0 + ca]);
            cpcommit();
            cpwait<1>();
        } else {
            cpwait<0>();
        }
        __syncthreads();
        #pragma unroll
        for (int kc = 0; kc < 2; kc++) {
            uint32_t af[4];
            ldsm4(af, sptr(&sA[buf][wm * 16 + lr_a][kc * 16 + lc_a]));
            #pragma unroll
            for (int np = 0; np < 2; np++) {
                uint32_t bfr[4];
                ldsm4(bfr, sptr(&sB[buf][wn * 32 + np * 16 + lr_b][kc * 16 + lc_b]));
                mma16816(acc[2 * np], af, bfr[0], bfr[1]);
                mma16816(acc[2 * np + 1], af, bfr[2], bfr[3]);
            }
        }
        __syncthreads();
    }

    float sc = a_proj_a[0] * a_proj_w[0];
    #pragma unroll
    for (int jj = 0; jj < 4; jj++)
        #pragma unroll
        for (int h2 = 0; h2 < 2; h2++) {
            int row = m0 + wm * 16 + gr + h2 * 8;
            int col = n0 + wn * 32 + jj * 8 + gc;
            float2 r2;
            r2.x = acc[jj][2 * h2] * sc + bproj[col];
            r2.y = acc[jj][2 * h2 + 1] * sc + bproj[col + 1];
            *(float2*)&out[(size_t)row * CC + col] = r2;
        }
}

// ---------------- launch ----------------
extern "C" void kernel_launch(void* const* d_in, const int* in_sizes, int n_in,
                              void* d_out, int out_size) {
    const float* x        = (const float*)d_in[0];
    const float* wqkv     = (const float*)d_in[1];
    const float* wproj    = (const float*)d_in[2];
    const float* bproj    = (const float*)d_in[3];
    const float* a_qkv_w  = (const float*)d_in[4];
    const float* a_qkv_a  = (const float*)d_in[5];
    const float* a_proj_w = (const float*)d_in[6];
    const float* a_proj_a = (const float*)d_in[7];
    const float* a_q      = (const float*)d_in[8];
    const float* a_k      = (const float*)d_in[9];
    const float* a_v      = (const float*)d_in[10];
    const float* a_attn   = (const float*)d_in[11];
    const float* a_attn2  = (const float*)d_in[12];
    float* out = (float*)d_out;

    k_quant<<<(MM * CC / 4 + 255) / 256, 256>>>(x, wqkv, wproj, a_qkv_w, a_proj_w, a_qkv_a);
    k_qkv<<<dim3(64, 9), 256>>>(a_qkv_a, a_qkv_w, a_q, a_k, a_v);
    k_attn<<<dim3(32, 12), 128>>>(a_q, a_k, a_attn, a_attn2, a_v, a_proj_a);
    k_proj<<<dim3(64, 6), 256>>>(out, bproj, a_proj_a, a_proj_w);
}

// round 11
// speedup vs baseline: 1.1840x; 1.0203x over previous
#include <cuda_runtime.h>
#include <cuda_bf16.h>
#include <cstdint>
#include <math.h>

#define BB 2
#define NN 2048
#define CC 384
#define HH 6
#define DD 64
#define TCC 1152   // 3*C
#define MM 4096    // B*N

typedef __nv_bfloat16 bf16;

// ---------------- device scratch ----------------
__device__ bf16 g_wqkv[TCC * CC];
__device__ bf16 g_wproj[CC * CC];
__device__ bf16 g_xq[(size_t)MM * CC];
__device__ bf16 g_q[BB * HH * NN * DD];
__device__ bf16 g_k[BB * HH * NN * DD];
__device__ bf16 g_v[BB * HH * NN * DD];
__device__ bf16 g_o[(size_t)MM * CC];

// ---------------- helpers ----------------
__device__ __forceinline__ float qlvl(float x, float inv_alpha) {
    float s = x * inv_alpha;
    s = fminf(fmaxf(s, -128.f), 127.f);
    return rintf(s);
}

__device__ __forceinline__ void mma16816(float* c, const uint32_t* a,
                                         uint32_t b0, uint32_t b1) {
    asm volatile(
        "mma.sync.aligned.m16n8k16.row.col.f32.bf16.bf16.f32 "
        "{%0,%1,%2,%3}, {%4,%5,%6,%7}, {%8,%9}, {%0,%1,%2,%3};\n"
        : "+f"(c[0]), "+f"(c[1]), "+f"(c[2]), "+f"(c[3])
        : "r"(a[0]), "r"(a[1]), "r"(a[2]), "r"(a[3]), "r"(b0), "r"(b1));
}

__device__ __forceinline__ uint32_t sptr(const void* p) {
    return (uint32_t)__cvta_generic_to_shared(p);
}

__device__ __forceinline__ void ldsm4(uint32_t* r, uint32_t addr) {
    asm volatile("ldmatrix.sync.aligned.m8n8.x4.shared.b16 {%0,%1,%2,%3},[%4];\n"
                 : "=r"(r[0]), "=r"(r[1]), "=r"(r[2]), "=r"(r[3]) : "r"(addr));
}

__device__ __forceinline__ void ldsm4t(uint32_t* r, uint32_t addr) {
    asm volatile("ldmatrix.sync.aligned.m8n8.x4.trans.shared.b16 {%0,%1,%2,%3},[%4];\n"
                 : "=r"(r[0]), "=r"(r[1]), "=r"(r[2]), "=r"(r[3]) : "r"(addr));
}

__device__ __forceinline__ void cpa16(uint32_t d, const void* s) {
    asm volatile("cp.async.cg.shared.global [%0], [%1], 16;\n" :: "r"(d), "l"(s));
}
__device__ __forceinline__ void cpcommit() {
    asm volatile("cp.async.commit_group;\n");
}
template <int N>
__device__ __forceinline__ void cpwait() {
    asm volatile("cp.async.wait_group %0;\n" :: "n"(N));
}

// ---------------- kernel 1: quantize weights + x to bf16 levels ----------------
__global__ __launch_bounds__(256) void k_quant(
        const float* __restrict__ x,
        const float* __restrict__ wqkv, const float* __restrict__ wproj,
        const float* __restrict__ a_qkv_w, const float* __restrict__ a_proj_w,
        const float* __restrict__ a_qkv_a) {
    float i1 = 1.f / a_qkv_w[0];
    float i2 = 1.f / a_proj_w[0];
    float i3 = 1.f / a_qkv_a[0];
    int i4 = (blockIdx.x * 256 + threadIdx.x) * 4;

    if (i4 < MM * CC) {
        float4 v = *(const float4*)&x[i4];
        __nv_bfloat162 p0, p1;
        p0.x = __float2bfloat16(qlvl(v.x, i3));
        p0.y = __float2bfloat16(qlvl(v.y, i3));
        p1.x = __float2bfloat16(qlvl(v.z, i3));
        p1.y = __float2bfloat16(qlvl(v.w, i3));
        *(__nv_bfloat162*)&g_xq[i4] = p0;
        *(__nv_bfloat162*)&g_xq[i4 + 2] = p1;
    }
    if (i4 < TCC * CC) {
        float4 v = *(const float4*)&wqkv[i4];
        __nv_bfloat162 p0, p1;
        p0.x = __float2bfloat16(qlvl(v.x, i1));
        p0.y = __float2bfloat16(qlvl(v.y, i1));
        p1.x = __float2bfloat16(qlvl(v.z, i1));
        p1.y = __float2bfloat16(qlvl(v.w, i1));
        *(__nv_bfloat162*)&g_wqkv[i4] = p0;
        *(__nv_bfloat162*)&g_wqkv[i4 + 2] = p1;
    }
    if (i4 < CC * CC) {
        float4 v = *(const float4*)&wproj[i4];
        __nv_bfloat162 p0, p1;
        p0.x = __float2bfloat16(qlvl(v.x, i2));
        p0.y = __float2bfloat16(qlvl(v.y, i2));
        p1.x = __float2bfloat16(qlvl(v.z, i2));
        p1.y = __float2bfloat16(qlvl(v.w, i2));
        *(__nv_bfloat162*)&g_wproj[i4] = p0;
        *(__nv_bfloat162*)&g_wproj[i4 + 2] = p1;
    }
}

// ---------------- kernel 2: QKV GEMM 4096x1152x384, CTA 64x128, 3-stage, 1 sync/iter ----------------
__global__ __launch_bounds__(256) void k_qkv(
        const float* __restrict__ a_qkv_a, const float* __restrict__ a_qkv_w,
        const float* __restrict__ a_q, const float* __restrict__ a_k,
        const float* __restrict__ a_v) {
    __shared__ bf16 sA[3][64][40];
    __shared__ bf16 sB[3][128][40];

    int tid = threadIdx.x, lane = tid & 31, wid = tid >> 5;
    int wm = wid & 3, wn = wid >> 2;
    int gr = lane >> 2, gc = (lane & 3) * 2;
    int lr_a = lane & 15, lc_a = (lane >> 4) << 3;
    int lr_b = ((lane >> 4) << 3) + (lane & 7), lc_b = ((lane >> 3) & 1) << 3;
    int m0 = blockIdx.x * 64, n0 = blockIdx.y * 128;

    int ra = tid >> 2, ca = (tid & 3) * 8;

    float acc[8][4];
    #pragma unroll
    for (int i = 0; i < 8; i++)
        #pragma unroll
        for (int c = 0; c < 4; c++) acc[i][c] = 0.f;

    // prologue: prefetch kt = 0, 1
    #pragma unroll
    for (int p = 0; p < 2; p++) {
        int kc0 = p * 32;
        cpa16(sptr(&sA[p][ra][ca]), &g_xq[(size_t)(m0 + ra) * CC + kc0 + ca]);
        cpa16(sptr(&sB[p][ra][ca]), &g_wqkv[(size_t)(n0 + ra) * CC + kc0 + ca]);
        cpa16(sptr(&sB[p][ra + 64][ca]), &g_wqkv[(size_t)(n0 + ra + 64) * CC + kc0 + ca]);
        cpcommit();
    }

    for (int kt = 0; kt < 12; kt++) {
        if (kt <= 9) cpwait<1>(); else cpwait<0>();
        __syncthreads();
        if (kt <= 9) {
            int st = (kt + 2) % 3, kc0 = (kt + 2) * 32;
            cpa16(sptr(&sA[st][ra][ca]), &g_xq[(size_t)(m0 + ra) * CC + kc0 + ca]);
            cpa16(sptr(&sB[st][ra][ca]), &g_wqkv[(size_t)(n0 + ra) * CC + kc0 + ca]);
            cpa16(sptr(&sB[st][ra + 64][ca]), &g_wqkv[(size_t)(n0 + ra + 64) * CC + kc0 + ca]);
            cpcommit();
        }
        int buf = kt % 3;
        #pragma unroll
        for (int kc = 0; kc < 2; kc++) {
            uint32_t af[4];
            ldsm4(af, sptr(&sA[buf][wm * 16 + lr_a][kc * 16 + lc_a]));
            #pragma unroll
            for (int np = 0; np < 4; np++) {
                uint32_t bfr[4];
                ldsm4(bfr, sptr(&sB[buf][wn * 64 + np * 16 + lr_b][kc * 16 + lc_b]));
                mma16816(acc[2 * np], af, bfr[0], bfr[1]);
                mma16816(acc[2 * np + 1], af, bfr[2], bfr[3]);
            }
        }
    }

    int which = (n0 >= 768) ? 2 : (n0 >= 384 ? 1 : 0);
    const float* a3 = (which == 0) ? a_q : (which == 1 ? a_k : a_v);
    float inv3 = 1.f / a3[0];
    float sAB = a_qkv_a[0] * a_qkv_w[0];
    bf16* dst = (which == 0) ? g_q : (which == 1 ? g_k : g_v);
    int ncol0 = n0 - which * CC;
    #pragma unroll
    for (int nc = 0; nc < 8; nc++)
        #pragma unroll
        for (int h2 = 0; h2 < 2; h2++) {
            int row = m0 + wm * 16 + gr + h2 * 8;
            int col = ncol0 + wn * 64 + nc * 8 + gc;
            int b = row >> 11, n = row & 2047;
            int h = col >> 6, d = col & 63;
            __nv_bfloat162 pr;
            pr.x = __float2bfloat16(qlvl(acc[nc][2 * h2] * sAB, inv3));
            pr.y = __float2bfloat16(qlvl(acc[nc][2 * h2 + 1] * sAB, inv3));
            *(__nv_bfloat162*)&dst[(((size_t)(b * HH + h)) * NN + n) * DD + d] = pr;
        }
}

// ---------------- kernel 3: fused attention, 64 Q rows/CTA, 4 warps, fixed m ----------------
// pass 1: 4-stage K ring (issue-ahead 3); pass 2: 2-stage K+V; 1 syncthreads per iter.
__global__ __launch_bounds__(128) void k_attn(
        const float* __restrict__ a_q, const float* __restrict__ a_k,
        const float* __restrict__ a_attn, const float* __restrict__ a_attn2,
        const float* __restrict__ a_v, const float* __restrict__ a_proj_a) {
    __shared__ bf16 stg[4][64][72];
    __shared__ float lut[256];

    int tid = threadIdx.x, lane = tid & 31, wid = tid >> 5;
    int gr = lane >> 2, gc = (lane & 3) * 2;
    int lr_a = lane & 15, lc_a = (lane >> 4) << 3;
    int lr_b = ((lane >> 4) << 3) + (lane & 7), lc_b = ((lane >> 3) & 1) << 3;
    int bh = blockIdx.y;
    int rt0 = blockIdx.x * 64;
    int wr = wid * 16;

    float aat = a_attn[0];
    float fsc = a_q[0] * a_k[0] * 0.125f / aat;   // scale = D^-0.5 = 1/8

    #pragma unroll
    for (int i = tid; i < 256; i += 128) lut[i] = expf(-(float)i * aat);

    const bf16* kbase = g_k + (size_t)bh * NN * DD;
    const bf16* vbase = g_v + (size_t)bh * NN * DD;

    // stage Q into stg[0], build resident A fragments
    const bf16* qptr = g_q + ((size_t)bh * NN + rt0) * DD;
    #pragma unroll
    for (int t = 0; t < 4; t++) {
        int idx = tid + t * 128;
        int r = idx >> 3, c8 = (idx & 7) * 8;
        *(uint4*)&stg[0][r][c8] = *(const uint4*)&qptr[(size_t)r * DD + c8];
    }
    __syncthreads();
    uint32_t qf[4][4];
    #pragma unroll
    for (int kc = 0; kc < 4; kc++)
        ldsm4(qf[kc], sptr(&stg[0][wr + lr_a][kc * 16 + lc_a]));
    __syncthreads();

    float tl[2] = {0.f, 0.f};

    // pass-1 prologue: prefetch K tiles 0,1,2 into stages 0,1,2
    #pragma unroll
    for (int p = 0; p < 3; p++) {
        const bf16* kp = kbase + (size_t)p * 64 * DD;
        #pragma unroll
        for (int t = 0; t < 4; t++) {
            int idx = tid + t * 128;
            int r = idx >> 3, c8 = (idx & 7) * 8;
            cpa16(sptr(&stg[p][r][c8]), &kp[(size_t)r * DD + c8]);
        }
        cpcommit();
    }

    // ---------- pass 1: row sums of exp((l-127)*a) ----------
    for (int ct = 0; ct < 32; ct++) {
        if (ct <= 28) cpwait<2>(); else cpwait<0>();
        __syncthreads();
        if (ct <= 28) {
            const bf16* kp = kbase + (size_t)(ct + 3) * 64 * DD;
            int st = (ct + 3) & 3;
            #pragma unroll
            for (int t = 0; t < 4; t++) {
                int idx = tid + t * 128;
                int r = idx >> 3, c8 = (idx & 7) * 8;
                cpa16(sptr(&stg[st][r][c8]), &kp[(size_t)r * DD + c8]);
            }
            cpcommit();
        }
        bf16(*Kb)[72] = stg[ct & 3];

        float sacc[8][4];
        #pragma unroll
        for (int i = 0; i < 8; i++)
            #pragma unroll
            for (int c = 0; c < 4; c++) sacc[i][c] = 0.f;
        #pragma unroll
        for (int ks = 0; ks < 4; ks++)
            #pragma unroll
            for (int np = 0; np < 4; np++) {
                uint32_t bfr[4];
                ldsm4(bfr, sptr(&Kb[np * 16 + lr_b][ks * 16 + lc_b]));
                mma16816(sacc[2 * np], qf[ks], bfr[0], bfr[1]);
                mma16816(sacc[2 * np + 1], qf[ks], bfr[2], bfr[3]);
            }

        #pragma unroll
        for (int nc = 0; nc < 8; nc++)
            #pragma unroll
            for (int h2 = 0; h2 < 2; h2++) {
                int l0 = __float2int_rn(fminf(fmaxf(sacc[nc][2 * h2] * fsc, -128.f), 127.f));
                int l1 = __float2int_rn(fminf(fmaxf(sacc[nc][2 * h2 + 1] * fsc, -128.f), 127.f));
                tl[h2] += lut[127 - l0] + lut[127 - l1];
            }
    }

    // pass-2 prologue: K0 -> stg[0], V0 -> stg[2] (stages 0/2 not read since iters 28/30)
    #pragma unroll
    for (int t = 0; t < 4; t++) {
        int idx = tid + t * 128;
        int r = idx >> 3, c8 = (idx & 7) * 8;
        cpa16(sptr(&stg[0][r][c8]), &kbase[(size_t)r * DD + c8]);
        cpa16(sptr(&stg[2][r][c8]), &vbase[(size_t)r * DD + c8]);
    }
    cpcommit();

    // quad sum-reduce (lanes of a quad share the row) -> lane-local inverse sums
    float inva2 = 1.f / a_attn2[0];
    float liq[2];
    #pragma unroll
    for (int h2 = 0; h2 < 2; h2++) {
        tl[h2] += __shfl_xor_sync(0xffffffff, tl[h2], 1);
        tl[h2] += __shfl_xor_sync(0xffffffff, tl[h2], 2);
        liq[h2] = inva2 / tl[h2];
    }

    // ---------- pass 2: recompute S, P in registers, P*V ----------
    float oacc[8][4];
    #pragma unroll
    for (int i = 0; i < 8; i++)
        #pragma unroll
        for (int c = 0; c < 4; c++) oacc[i][c] = 0.f;

    for (int ct = 0; ct < 32; ct++) {
        cpwait<0>();
        __syncthreads();
        if (ct < 31) {
            const bf16* kp = kbase + (size_t)(ct + 1) * 64 * DD;
            const bf16* vp = vbase + (size_t)(ct + 1) * 64 * DD;
            int stk = (ct + 1) & 1, stv = 2 + ((ct + 1) & 1);
            #pragma unroll
            for (int t = 0; t < 4; t++) {
                int idx = tid + t * 128;
                int r = idx >> 3, c8 = (idx & 7) * 8;
                cpa16(sptr(&stg[stk][r][c8]), &kp[(size_t)r * DD + c8]);
                cpa16(sptr(&stg[stv][r][c8]), &vp[(size_t)r * DD + c8]);
            }
            cpcommit();
        }
        bf16(*Kb)[72] = stg[ct & 1];
        bf16(*Vb)[72] = stg[2 + (ct & 1)];

        float sacc[8][4];
        #pragma unroll
        for (int i = 0; i < 8; i++)
            #pragma unroll
            for (int c = 0; c < 4; c++) sacc[i][c] = 0.f;
        #pragma unroll
        for (int ks = 0; ks < 4; ks++)
            #pragma unroll
            for (int np = 0; np < 4; np++) {
                uint32_t bfr[4];
                ldsm4(bfr, sptr(&Kb[np * 16 + lr_b][ks * 16 + lc_b]));
                mma16816(sacc[2 * np], qf[ks], bfr[0], bfr[1]);
                mma16816(sacc[2 * np + 1], qf[ks], bfr[2], bfr[3]);
            }

        // S fragments (f32) -> P level fragments (bf16 A-layout), in registers
        uint32_t pf[4][4];
        #pragma unroll
        for (int kc = 0; kc < 4; kc++) {
            int nc = 2 * kc, ncb = 2 * kc + 1;
            #pragma unroll
            for (int slot = 0; slot < 4; slot++) {
                int src = (slot & 2) ? ncb : nc;
                int h2 = slot & 1;
                float s0 = (h2 ? sacc[src][2] : sacc[src][0]);
                float s1 = (h2 ? sacc[src][3] : sacc[src][1]);
                int l0 = __float2int_rn(fminf(fmaxf(s0 * fsc, -128.f), 127.f));
                int l1 = __float2int_rn(fminf(fmaxf(s1 * fsc, -128.f), 127.f));
                float p0 = rintf(fminf(lut[127 - l0] * liq[h2], 127.f));
                float p1 = rintf(fminf(lut[127 - l1] * liq[h2], 127.f));
                __nv_bfloat162 pr;
                pr.x = __float2bfloat16(p0);
                pr.y = __float2bfloat16(p1);
                pf[kc][slot] = *(uint32_t*)&pr;
            }
        }

        // P (16x64) x V (64x64): B fragments via ldmatrix.trans
        #pragma unroll
        for (int ks = 0; ks < 4; ks++)
            #pragma unroll
            for (int np = 0; np < 4; np++) {
                uint32_t bfr[4];
                ldsm4t(bfr, sptr(&Vb[ks * 16 + lr_a][np * 16 + lc_a]));
                mma16816(oacc[2 * np], pf[ks], bfr[0], bfr[1]);
                mma16816(oacc[2 * np + 1], pf[ks], bfr[2], bfr[3]);
            }
    }

    // epilogue: scale by a_attn2*a_v, quantize with a_proj_a, store [B,N,C] levels
    int b = bh / HH, h = bh % HH;
    float so = a_attn2[0] * a_v[0];
    float invpa = 1.f / a_proj_a[0];
    #pragma unroll
    for (int nc = 0; nc < 8; nc++)
        #pragma unroll
        for (int h2 = 0; h2 < 2; h2++) {
            int n = rt0 + wr + gr + h2 * 8;
            int d = nc * 8 + gc;
            __nv_bfloat162 pr;
            pr.x = __float2bfloat16(qlvl(oacc[nc][2 * h2] * so, invpa));
            pr.y = __float2bfloat16(qlvl(oacc[nc][2 * h2 + 1] * so, invpa));
            *(__nv_bfloat162*)&g_o[((size_t)(b * NN + n)) * CC + h * 64 + d] = pr;
        }
}

// ---------------- kernel 4: projection GEMM 4096x384x384 + bias, CTA 64x64, 3-stage ----------------
__global__ __launch_bounds__(256) void k_proj(
        float* __restrict__ out, const float* __restrict__ bproj,
        const float* __restrict__ a_proj_a, const float* __restrict__ a_proj_w) {
    __shared__ bf16 sA[3][64][40];
    __shared__ bf16 sB[3][64][40];

    int tid = threadIdx.x, lane = tid & 31, wid = tid >> 5;
    int wm = wid & 3, wn = wid >> 2;
    int gr = lane >> 2, gc = (lane & 3) * 2;
    int lr_a = lane & 15, lc_a = (lane >> 4) << 3;
    int lr_b = ((lane >> 4) << 3) + (lane & 7), lc_b = ((lane >> 3) & 1) << 3;
    int m0 = blockIdx.x * 64, n0 = blockIdx.y * 64;

    int ra = tid >> 2, ca = (tid & 3) * 8;

    float acc[4][4];
    #pragma unroll
    for (int i = 0; i < 4; i++)
        #pragma unroll
        for (int c = 0; c < 4; c++) acc[i][c] = 0.f;

    #pragma unroll
    for (int p = 0; p < 2; p++) {
        int kc0 = p * 32;
        cpa16(sptr(&sA[p][ra][ca]), &g_o[(size_t)(m0 + ra) * CC + kc0 + ca]);
        cpa16(sptr(&sB[p][ra][ca]), &g_wproj[(size_t)(n0 + ra) * CC + kc0 + ca]);
        cpcommit();
    }

    for (int kt = 0; kt < 12; kt++) {
        if (kt <= 9) cpwait<1>(); else cpwait<0>();
        __syncthreads();
        if (kt <= 9) {
            int st = (kt + 2) % 3, kc0 = (kt + 2) * 32;
            cpa16(sptr(&sA[st][ra][ca]), &g_o[(size_t)(m0 + ra) * CC + kc0 + ca]);
            cpa16(sptr(&sB[st][ra][ca]), &g_wproj[(size_t)(n0 + ra) * CC + kc0 + ca]);
            cpcommit();
        }
        int buf = kt % 3;
        #pragma unroll
        for (int kc = 0; kc < 2; kc++) {
            uint32_t af[4];
            ldsm4(af, sptr(&sA[buf][wm * 16 + lr_a][kc * 16 + lc_a]));
            #pragma unroll
            for (int np = 0; np < 2; np++) {
                uint32_t bfr[4];
                ldsm4(bfr, sptr(&sB[buf][wn * 32 + np * 16 + lr_b][kc * 16 + lc_b]));
                mma16816(acc[2 * np], af, bfr[0], bfr[1]);
                mma16816(acc[2 * np + 1], af, bfr[2], bfr[3]);
            }
        }
    }

    float sc = a_proj_a[0] * a_proj_w[0];
    #pragma unroll
    for (int jj = 0; jj < 4; jj++)
        #pragma unroll
        for (int h2 = 0; h2 < 2; h2++) {
            int row = m0 + wm * 16 + gr + h2 * 8;
            int col = n0 + wn * 32 + jj * 8 + gc;
            float2 r2;
            r2.x = acc[jj][2 * h2] * sc + bproj[col];
            r2.y = acc[jj][2 * h2 + 1] * sc + bproj[col + 1];
            *(float2*)&out[(size_t)row * CC + col] = r2;
        }
}

// ---------------- launch ----------------
extern "C" void kernel_launch(void* const* d_in, const int* in_sizes, int n_in,
                              void* d_out, int out_size) {
    const float* x        = (const float*)d_in[0];
    const float* wqkv     = (const float*)d_in[1];
    const float* wproj    = (const float*)d_in[2];
    const float* bproj    = (const float*)d_in[3];
    const float* a_qkv_w  = (const float*)d_in[4];
    const float* a_qkv_a  = (const float*)d_in[5];
    const float* a_proj_w = (const float*)d_in[6];
    const float* a_proj_a = (const float*)d_in[7];
    const float* a_q      = (const float*)d_in[8];
    const float* a_k      = (const float*)d_in[9];
    const float* a_v      = (const float*)d_in[10];
    const float* a_attn   = (const float*)d_in[11];
    const float* a_attn2  = (const float*)d_in[12];
    float* out = (float*)d_out;

    k_quant<<<(MM * CC / 4 + 255) / 256, 256>>>(x, wqkv, wproj, a_qkv_w, a_proj_w, a_qkv_a);
    k_qkv<<<dim3(64, 9), 256>>>(a_qkv_a, a_qkv_w, a_q, a_k, a_v);
    k_attn<<<dim3(32, 12), 128>>>(a_q, a_k, a_attn, a_attn2, a_v, a_proj_a);
    k_proj<<<dim3(64, 6), 256>>>(out, bproj, a_proj_a, a_proj_w);
}